// round 8
// baseline (speedup 1.0000x reference)
#include <cuda_runtime.h>
#include <math.h>
#include <stdint.h>

#define F    1024
#define NJ   64
#define C    256
#define HID  1024
#define H    8
#define D    128
#define M_TOT (NJ * F)      // 65536
#define EPSV 1e-6f

// Scratch (device globals — no allocation allowed in kernel_launch)
__device__ float g_Q[(size_t)M_TOT * HID];
__device__ float g_K[(size_t)M_TOT * HID];
__device__ float g_V[(size_t)M_TOT * HID];
__device__ float g_KVt[(size_t)NJ * H * D * D];  // KV transposed [n,h,d,m], tf32-rounded
__device__ float g_Ksum[(size_t)NJ * H * D];
__device__ float g_Wr[(size_t)3 * C * HID];      // tf32-rounded weights, native [k][n]

__device__ __forceinline__ float ftf32(float x) {
    float r;
    asm("cvt.rna.tf32.f32 %0, %1;" : "=f"(r) : "f"(x));
    return r;
}

__device__ __forceinline__ uint32_t smem_u32(const void* p) {
    uint32_t a;
    asm("{ .reg .u64 t; cvta.to.shared.u64 t, %1; cvt.u32.u64 %0, t; }"
        : "=r"(a) : "l"(p));
    return a;
}

__device__ __forceinline__ void cp16(uint32_t dst_smem, const void* src) {
    asm volatile("cp.async.cg.shared.global [%0], [%1], 16;"
                 :: "r"(dst_smem), "l"(__cvta_generic_to_global(src)) : "memory");
}
__device__ __forceinline__ void cp_commit() {
    asm volatile("cp.async.commit_group;" ::: "memory");
}
__device__ __forceinline__ void cp_wait0() {
    asm volatile("cp.async.wait_group 0;" ::: "memory");
}
__device__ __forceinline__ void cp_wait1() {
    asm volatile("cp.async.wait_group 1;" ::: "memory");
}

__device__ __forceinline__ void mma_tf32(float* c, const uint32_t* a,
                                         uint32_t b0, uint32_t b1) {
    asm volatile(
        "mma.sync.aligned.m16n8k8.row.col.f32.tf32.tf32.f32 "
        "{%0,%1,%2,%3}, {%4,%5,%6,%7}, {%8,%9}, {%0,%1,%2,%3};"
        : "+f"(c[0]), "+f"(c[1]), "+f"(c[2]), "+f"(c[3])
        : "r"(a[0]), "r"(a[1]), "r"(a[2]), "r"(a[3]), "r"(b0), "r"(b1));
}

// ---------------------------------------------------------------------------
// Prep: g_Wr = ftf32(W), same layout (Q,K,V concatenated).
// ---------------------------------------------------------------------------
__global__ __launch_bounds__(256) void wr_kernel(
    const float* __restrict__ Wq, const float* __restrict__ Wk,
    const float* __restrict__ Wv)
{
    const size_t elems = (size_t)C * HID;
    const size_t i4 = (size_t)blockIdx.x * 256 + threadIdx.x;
    const size_t per = elems / 4;
    const int w = (int)(i4 / per);
    const size_t off = (i4 % per) * 4;
    const float* W = (w == 0) ? Wq : ((w == 1) ? Wk : Wv);
    float4 v = *(const float4*)(W + off);
    v.x = ftf32(v.x); v.y = ftf32(v.y); v.z = ftf32(v.z); v.w = ftf32(v.w);
    *(float4*)(g_Wr + (size_t)w * elems + off) = v;
}

// ---------------------------------------------------------------------------
// Kernel 1: QKV projection, tf32 mma.sync, block tile 128(M)x256(N), BK=32.
// 8 warps (2 m x 4 n), warp tile 64x64. B double-buffered via cp.async.
// Grid (12, 512): the 12 blocks sharing an A tile are adjacent -> L2 reuse.
// ---------------------------------------------------------------------------
__global__ __launch_bounds__(256) void qkv_mma_kernel(
    const float* __restrict__ x,
    const float* __restrict__ bq, const float* __restrict__ bk,
    const float* __restrict__ bv)
{
    extern __shared__ float smem[];
    float (*As)[136] = (float(*)[136])smem;                 // 32 x 136
    float (*Bs2)[32][264] = (float(*)[32][264])(smem + 32 * 136);  // 2 x 32 x 264
    const uint32_t sB0 = smem_u32(&Bs2[0][0][0]);
    const uint32_t bufStride = 32 * 264 * 4;

    const int tid  = threadIdx.x;
    const int lane = tid & 31;
    const int warp = tid >> 5;
    const int wm   = warp & 1;
    const int wn   = warp >> 1;
    const int gr   = lane >> 2;
    const int gc   = lane & 3;

    const int by = blockIdx.x;      // 0..11
    const int bm = blockIdx.y;      // 0..511
    const int w  = by >> 2;         // 0=Q,1=K,2=V
    const int colbase = (by & 3) * 256;

    // A loader: row ar (0..127), half kq, 16 contiguous k-floats (64B)
    const int ar   = tid >> 1;
    const int kq   = tid & 1;
    const int am   = bm * 128 + ar;
    const int fidx = am & (F - 1);
    const int nidx = am >> 10;
    const float* ap = x + ((size_t)fidx * NJ + nidx) * C + kq * 16;

    // B cp.async: 2048 chunks/ktile; c = i*256+tid -> warp-contiguous
    const float* bsrc = g_Wr + (size_t)w * C * HID + colbase;
    int brow[8]; int bseg[8]; uint32_t bdst[8];
#pragma unroll
    for (int i = 0; i < 8; i++) {
        const int c = i * 256 + tid;
        brow[i] = c >> 6;
        bseg[i] = (c & 63) * 4;
        bdst[i] = sB0 + (uint32_t)(brow[i] * 264 + bseg[i]) * 4;
    }

    float acc[4][8][4];
#pragma unroll
    for (int mf = 0; mf < 4; mf++)
#pragma unroll
        for (int nf = 0; nf < 8; nf++)
#pragma unroll
            for (int i = 0; i < 4; i++) acc[mf][nf][i] = 0.f;

    // prologue: A(0) regs + B(0) -> buf 0
    float4 aR[4];
#pragma unroll
    for (int i = 0; i < 4; i++) aR[i] = *(const float4*)(ap + i * 4);
#pragma unroll
    for (int i = 0; i < 8; i++)
        cp16(bdst[i], bsrc + (size_t)brow[i] * HID + bseg[i]);
    cp_commit();

    for (int kt = 0; kt < 8; kt++) {
        const int cur = kt & 1;
        __syncthreads();               // compute(kt-1) done; As & Bs[cur] free
#pragma unroll
        for (int i = 0; i < 4; i++) {
            const int kb = kq * 16 + i * 4;
            As[kb + 0][ar] = ftf32(aR[i].x);
            As[kb + 1][ar] = ftf32(aR[i].y);
            As[kb + 2][ar] = ftf32(aR[i].z);
            As[kb + 3][ar] = ftf32(aR[i].w);
        }
        if (kt < 7) {
#pragma unroll
            for (int i = 0; i < 4; i++)
                aR[i] = *(const float4*)(ap + (kt + 1) * 32 + i * 4);
            const uint32_t off = (cur ^ 1) * bufStride;
#pragma unroll
            for (int i = 0; i < 8; i++)
                cp16(bdst[i] + off, bsrc + (size_t)((kt + 1) * 32 + brow[i]) * HID + bseg[i]);
            cp_commit();
            cp_wait1();                // group kt done; kt+1 still in flight
        } else {
            cp_wait0();
        }
        __syncthreads();

        float (*Bs)[264] = Bs2[cur];
#pragma unroll
        for (int ks = 0; ks < 4; ks++) {
            const int kk = ks * 8;
            uint32_t afr[4][4];
#pragma unroll
            for (int mf = 0; mf < 4; mf++) {
                const int m0 = wm * 64 + mf * 16;
                afr[mf][0] = __float_as_uint(As[kk + gc][m0 + gr]);
                afr[mf][1] = __float_as_uint(As[kk + gc][m0 + gr + 8]);
                afr[mf][2] = __float_as_uint(As[kk + gc + 4][m0 + gr]);
                afr[mf][3] = __float_as_uint(As[kk + gc + 4][m0 + gr + 8]);
            }
#pragma unroll
            for (int nf = 0; nf < 8; nf++) {
                const int n0 = wn * 64 + nf * 8;
                const uint32_t b0 = __float_as_uint(Bs[kk + gc][n0 + gr]);
                const uint32_t b1 = __float_as_uint(Bs[kk + gc + 4][n0 + gr]);
#pragma unroll
                for (int mf = 0; mf < 4; mf++)
                    mma_tf32(acc[mf][nf], afr[mf], b0, b1);
            }
        }
    }

    // Epilogue: bias + feature map
    const float* bias = (w == 0) ? bq : ((w == 1) ? bk : bv);
    float* OUT        = (w == 0) ? g_Q : ((w == 1) ? g_K : g_V);
    const bool fmap = (w < 2);
#pragma unroll
    for (int mf = 0; mf < 4; mf++) {
        const int mrow = bm * 128 + wm * 64 + mf * 16 + gr;
#pragma unroll
        for (int nf = 0; nf < 8; nf++) {
            const int col = colbase + wn * 64 + nf * 8 + 2 * gc;
            const float b0v = bias[col];
            const float b1v = bias[col + 1];
            float v0 = acc[mf][nf][0] + b0v;
            float v1 = acc[mf][nf][1] + b1v;
            float v2 = acc[mf][nf][2] + b0v;
            float v3 = acc[mf][nf][3] + b1v;
            if (fmap) {
                v0 = (v0 > 0.f) ? (v0 + 1.f) : __expf(v0);
                v1 = (v1 > 0.f) ? (v1 + 1.f) : __expf(v1);
                v2 = (v2 > 0.f) ? (v2 + 1.f) : __expf(v2);
                v3 = (v3 > 0.f) ? (v3 + 1.f) : __expf(v3);
            }
            *(float2*)&OUT[(size_t)mrow * HID + col]       = make_float2(v0, v1);
            *(float2*)&OUT[(size_t)(mrow + 8) * HID + col] = make_float2(v2, v3);
        }
    }
}

// ===================== kv kernel (R3 + transposed tf32 output) ===============
#define MMA_TILE_BODY(As, Bs, acc)                                            \
    _Pragma("unroll")                                                         \
    for (int ks = 0; ks < 4; ks++) {                                          \
        const int kk = ks * 8;                                                \
        uint32_t afr[2][4];                                                   \
        _Pragma("unroll")                                                     \
        for (int mf = 0; mf < 2; mf++) {                                      \
            const int m0 = wm2 * 32 + mf * 16;                                \
            afr[mf][0] = __float_as_uint(As[kk + gc][m0 + gr]);               \
            afr[mf][1] = __float_as_uint(As[kk + gc][m0 + gr + 8]);           \
            afr[mf][2] = __float_as_uint(As[kk + gc + 4][m0 + gr]);           \
            afr[mf][3] = __float_as_uint(As[kk + gc + 4][m0 + gr + 8]);       \
        }                                                                     \
        _Pragma("unroll")                                                     \
        for (int nf = 0; nf < 8; nf++) {                                      \
            const int n0 = wn2 * 64 + nf * 8;                                 \
            const uint32_t b0 = __float_as_uint(Bs[kk + gc][n0 + gr]);        \
            const uint32_t b1 = __float_as_uint(Bs[kk + gc + 4][n0 + gr]);    \
            mma_tf32(acc[0][nf], afr[0], b0, b1);                             \
            mma_tf32(acc[1][nf], afr[1], b0, b1);                             \
        }                                                                     \
    }

__global__ __launch_bounds__(256) void kv_mma_kernel()
{
    __shared__ float As[32][136];
    __shared__ float Bs[32][136];
    __shared__ float sKsum[128];

    const int tid  = threadIdx.x;
    const int lane = tid & 31;
    const int warp = tid >> 5;
    const int wm2  = warp & 3;
    const int wn2  = warp >> 2;
    const int gr   = lane >> 2;
    const int gc   = lane & 3;

    const int n = blockIdx.x, h = blockIdx.y;
    const size_t base = (size_t)n * F * HID + (size_t)h * D;

    const int sr = tid >> 3;
    const int c0 = (tid & 7) * 4;
    const float* vptr = g_V + base + (size_t)sr * HID + c0;
    const float* kptr = g_K + base + (size_t)sr * HID + c0;

    if (tid < 128) sKsum[tid] = 0.f;
    float4 kacc[4];
#pragma unroll
    for (int i = 0; i < 4; i++) kacc[i] = make_float4(0.f, 0.f, 0.f, 0.f);

    float acc[2][8][4];
#pragma unroll
    for (int mf = 0; mf < 2; mf++)
#pragma unroll
        for (int nf = 0; nf < 8; nf++)
#pragma unroll
            for (int i = 0; i < 4; i++) acc[mf][nf][i] = 0.f;

    for (int s0 = 0; s0 < F; s0 += 32) {
        float4 av[4], ak[4];
#pragma unroll
        for (int i = 0; i < 4; i++) {
            av[i] = *(const float4*)(vptr + (size_t)s0 * HID + i * 32);
            ak[i] = *(const float4*)(kptr + (size_t)s0 * HID + i * 32);
        }
        __syncthreads();
#pragma unroll
        for (int i = 0; i < 4; i++) {
            float4 tv = av[i], tk = ak[i];
            kacc[i].x += tk.x; kacc[i].y += tk.y; kacc[i].z += tk.z; kacc[i].w += tk.w;
            tv.x = ftf32(tv.x); tv.y = ftf32(tv.y); tv.z = ftf32(tv.z); tv.w = ftf32(tv.w);
            tk.x = ftf32(tk.x); tk.y = ftf32(tk.y); tk.z = ftf32(tk.z); tk.w = ftf32(tk.w);
            *(float4*)&As[sr][c0 + i * 32] = tv;
            *(float4*)&Bs[sr][c0 + i * 32] = tk;
        }
        __syncthreads();

        MMA_TILE_BODY(As, Bs, acc)
    }

#pragma unroll
    for (int i = 0; i < 4; i++) {
        atomicAdd(&sKsum[c0 + i * 32 + 0], kacc[i].x);
        atomicAdd(&sKsum[c0 + i * 32 + 1], kacc[i].y);
        atomicAdd(&sKsum[c0 + i * 32 + 2], kacc[i].z);
        atomicAdd(&sKsum[c0 + i * 32 + 3], kacc[i].w);
    }
    __syncthreads();

    const size_t nh = (size_t)n * H + h;
    if (tid < 128) g_Ksum[nh * D + tid] = sKsum[tid];

    // Transposed tf32 output: g_KVt[nh][d][m] = ftf32(KV[m][d])
    const size_t kvbase = nh * D * D;
#pragma unroll
    for (int mf = 0; mf < 2; mf++) {
        const int mrow = wm2 * 32 + mf * 16 + gr;
#pragma unroll
        for (int nf = 0; nf < 8; nf++) {
            const int ncol = wn2 * 64 + nf * 8 + 2 * gc;
            g_KVt[kvbase + (size_t)(ncol    ) * D + mrow    ] = ftf32(acc[mf][nf][0]);
            g_KVt[kvbase + (size_t)(ncol + 1) * D + mrow    ] = ftf32(acc[mf][nf][1]);
            g_KVt[kvbase + (size_t)(ncol    ) * D + mrow + 8] = ftf32(acc[mf][nf][2]);
            g_KVt[kvbase + (size_t)(ncol + 1) * D + mrow + 8] = ftf32(acc[mf][nf][3]);
        }
    }
}

// ---------------------------------------------------------------------------
// Kernel 3 v2: KV resident in smem; grid (4, NJ, H), 2 l-tiles/block.
// A double-buffered with register prefetch, 1 sync per d-tile.
// ---------------------------------------------------------------------------
__global__ __launch_bounds__(256) void out_mma_kernel(float* __restrict__ out)
{
    extern __shared__ float sm[];
    float (*Bs4)[32][136] = (float(*)[32][136])sm;                  // KVt [dt][dk][m]
    float (*As2)[32][136] = (float(*)[32][136])(sm + 4 * 32 * 136); // A   [buf][dk][l]
    float* sKs = sm + 4 * 32 * 136 + 2 * 32 * 136;
    float* sZ  = sKs + 128;

    const int tid  = threadIdx.x;
    const int lane = tid & 31;
    const int warp = tid >> 5;
    const int wm2  = warp & 3;
    const int wn2  = warp >> 2;
    const int gr   = lane >> 2;
    const int gc   = lane & 3;

    const int lt4 = blockIdx.x;                 // 0..3 (l-range of 256)
    const int n = blockIdx.y, h = blockIdx.z;
    const size_t nh = (size_t)n * H + h;
    const size_t kvbase = nh * (size_t)D * D;

    // Load Ksum + KVt (resident)
    if (tid < 128) sKs[tid] = g_Ksum[nh * D + tid];
    {
        const float* kvt = g_KVt + kvbase;
        const int d  = tid >> 1;
        const int ms = (tid & 1) * 64;
#pragma unroll
        for (int i = 0; i < 16; i++) {
            float4 v = *(const float4*)(kvt + (size_t)d * D + ms + i * 4);
            *(float4*)&Bs4[d >> 5][d & 31][ms + i * 4] = v;
        }
    }
    __syncthreads();

    for (int lti = 0; lti < 2; lti++) {
        const int l0 = lt4 * 256 + lti * 128;
        const size_t qbase = ((size_t)n * F + l0) * HID + (size_t)h * D;

        // Z: one warp per row (16 rows/warp), coalesced float4 + shfl reduce
        {
            float4 kv4 = *(const float4*)&sKs[lane * 4];
#pragma unroll
            for (int r8 = 0; r8 < 16; r8++) {
                const int row = warp * 16 + r8;
                const float* q = g_Q + qbase + (size_t)row * HID;
                float4 qv = *(const float4*)(q + lane * 4);
                float dd = qv.x * kv4.x + qv.y * kv4.y + qv.z * kv4.z + qv.w * kv4.w;
#pragma unroll
                for (int off = 16; off; off >>= 1) dd += __shfl_xor_sync(0xffffffffu, dd, off);
                if (lane == 0) sZ[row] = 1.f / (dd + EPSV);
            }
        }

        const int lr  = tid >> 1;
        const int d16 = (tid & 1) * 16;
        const float* qp = g_Q + qbase + (size_t)lr * HID + d16;

        float acc[2][8][4];
#pragma unroll
        for (int mf = 0; mf < 2; mf++)
#pragma unroll
            for (int nf = 0; nf < 8; nf++)
#pragma unroll
                for (int i = 0; i < 4; i++) acc[mf][nf][i] = 0.f;

        // prefetch A d-tile 0
        float4 aR[4];
#pragma unroll
        for (int i = 0; i < 4; i++) aR[i] = *(const float4*)(qp + i * 4);

        for (int dt = 0; dt < 4; dt++) {
            const int cur = dt & 1;
            float (*As)[136] = As2[cur];
#pragma unroll
            for (int i = 0; i < 4; i++) {
                const int kb = d16 + i * 4;
                As[kb + 0][lr] = ftf32(aR[i].x);
                As[kb + 1][lr] = ftf32(aR[i].y);
                As[kb + 2][lr] = ftf32(aR[i].z);
                As[kb + 3][lr] = ftf32(aR[i].w);
            }
            if (dt < 3) {
#pragma unroll
                for (int i = 0; i < 4; i++)
                    aR[i] = *(const float4*)(qp + (dt + 1) * 32 + i * 4);
            }
            __syncthreads();

            float (*Bs)[136] = Bs4[dt];
            MMA_TILE_BODY(As, Bs, acc)
        }

        // Epilogue
#pragma unroll
        for (int mf = 0; mf < 2; mf++) {
            const int row = wm2 * 32 + mf * 16 + gr;
            const float z0 = sZ[row];
            const float z1 = sZ[row + 8];
            const size_t ob0 = (size_t)(l0 + row) * (NJ * HID) + (size_t)n * HID + (size_t)h * D;
            const size_t ob1 = (size_t)(l0 + row + 8) * (NJ * HID) + (size_t)n * HID + (size_t)h * D;
#pragma unroll
            for (int nf = 0; nf < 8; nf++) {
                const int ncol = wn2 * 64 + nf * 8 + 2 * gc;
                *(float2*)&out[ob0 + ncol] =
                    make_float2(acc[mf][nf][0] * z0, acc[mf][nf][1] * z0);
                *(float2*)&out[ob1 + ncol] =
                    make_float2(acc[mf][nf][2] * z1, acc[mf][nf][3] * z1);
            }
        }
        __syncthreads();   // before next lti overwrites sZ / As buffers
    }
}

// ---------------------------------------------------------------------------
extern "C" void kernel_launch(void* const* d_in, const int* in_sizes, int n_in,
                              void* d_out, int out_size)
{
    const float* x  = (const float*)d_in[0];
    const float* Wq = (const float*)d_in[1];
    const float* bq = (const float*)d_in[2];
    const float* Wk = (const float*)d_in[3];
    const float* bk = (const float*)d_in[4];
    const float* Wv = (const float*)d_in[5];
    const float* bv = (const float*)d_in[6];
    float* out = (float*)d_out;

    wr_kernel<<<3 * C * HID / 4 / 256, 256>>>(Wq, Wk, Wv);

    // QKV: grid (12, 512) — A-tile sharers adjacent for L2 reuse
    const int smem1 = (32 * 136 + 2 * 32 * 264) * 4;   // 84,992 B
    cudaFuncSetAttribute(qkv_mma_kernel,
                         cudaFuncAttributeMaxDynamicSharedMemorySize, smem1);
    dim3 g1(12, M_TOT / 128);
    qkv_mma_kernel<<<g1, 256, smem1>>>(x, bq, bk, bv);

    dim3 g2(NJ, H);
    kv_mma_kernel<<<g2, 256>>>();

    // out: KV resident
    const int smem3 = (4 * 32 * 136 + 2 * 32 * 136 + 256) * 4;   // 105,472 B
    cudaFuncSetAttribute(out_mma_kernel,
                         cudaFuncAttributeMaxDynamicSharedMemorySize, smem3);
    dim3 g3(4, NJ, H);
    out_mma_kernel<<<g3, 256, smem3>>>(out);
}

// round 9
// speedup vs baseline: 1.0977x; 1.0977x over previous
#include <cuda_runtime.h>
#include <math.h>
#include <stdint.h>

#define F    1024
#define NJ   64
#define C    256
#define HID  1024
#define H    8
#define D    128
#define M_TOT (NJ * F)      // 65536
#define EPSV 1e-6f

// Scratch (device globals — no allocation allowed in kernel_launch)
__device__ float g_Q[(size_t)M_TOT * HID];
__device__ float g_K[(size_t)M_TOT * HID];
__device__ float g_V[(size_t)M_TOT * HID];
__device__ float g_KV[(size_t)NJ * H * D * D];
__device__ float g_Ksum[(size_t)NJ * H * D];
__device__ float g_Xr[(size_t)M_TOT * C];      // x as [m][k], tf32-rounded (m = n*F+f)
__device__ float g_Wt[(size_t)3 * HID * C];    // W as [w][n][k], tf32-rounded (transposed)

__device__ __forceinline__ float ftf32(float x) {
    float r;
    asm("cvt.rna.tf32.f32 %0, %1;" : "=f"(r) : "f"(x));
    return r;
}

__device__ __forceinline__ uint32_t smem_u32(const void* p) {
    uint32_t a;
    asm("{ .reg .u64 t; cvta.to.shared.u64 t, %1; cvt.u32.u64 %0, t; }"
        : "=r"(a) : "l"(p));
    return a;
}

__device__ __forceinline__ void cp16(uint32_t dst_smem, const void* src) {
    asm volatile("cp.async.cg.shared.global [%0], [%1], 16;"
                 :: "r"(dst_smem), "l"(__cvta_generic_to_global(src)) : "memory");
}
__device__ __forceinline__ void cp_commit() {
    asm volatile("cp.async.commit_group;" ::: "memory");
}
template <int N>
__device__ __forceinline__ void cp_wait() {
    asm volatile("cp.async.wait_group %0;" :: "n"(N) : "memory");
}

__device__ __forceinline__ void mma_tf32(float* c, const uint32_t* a,
                                         uint32_t b0, uint32_t b1) {
    asm volatile(
        "mma.sync.aligned.m16n8k8.row.col.f32.tf32.tf32.f32 "
        "{%0,%1,%2,%3}, {%4,%5,%6,%7}, {%8,%9}, {%0,%1,%2,%3};"
        : "+f"(c[0]), "+f"(c[1]), "+f"(c[2]), "+f"(c[3])
        : "r"(a[0]), "r"(a[1]), "r"(a[2]), "r"(a[3]), "r"(b0), "r"(b1));
}

__device__ __forceinline__ void ldsm4(uint32_t& r0, uint32_t& r1,
                                      uint32_t& r2, uint32_t& r3, uint32_t addr) {
    asm volatile("ldmatrix.sync.aligned.m8n8.x4.shared.b16 {%0,%1,%2,%3}, [%4];"
                 : "=r"(r0), "=r"(r1), "=r"(r2), "=r"(r3) : "r"(addr));
}

// ---------------------------------------------------------------------------
// Prep A: x[f][n][c] -> g_Xr[m][k] (m = n*F+f), tf32-rounded. Coalesced both sides.
// ---------------------------------------------------------------------------
__global__ __launch_bounds__(256) void xr_kernel(const float* __restrict__ x)
{
    const int warp = threadIdx.x >> 5, lane = threadIdx.x & 31;
    const int m = blockIdx.x * 8 + warp;
    const int f = m & (F - 1), n = m >> 10;
    const float* src = x + ((size_t)f * NJ + n) * C + lane * 8;
    float* dst = g_Xr + (size_t)m * C + lane * 8;
    float4 v0 = *(const float4*)(src);
    float4 v1 = *(const float4*)(src + 4);
    v0.x = ftf32(v0.x); v0.y = ftf32(v0.y); v0.z = ftf32(v0.z); v0.w = ftf32(v0.w);
    v1.x = ftf32(v1.x); v1.y = ftf32(v1.y); v1.z = ftf32(v1.z); v1.w = ftf32(v1.w);
    *(float4*)(dst)     = v0;
    *(float4*)(dst + 4) = v1;
}

// ---------------------------------------------------------------------------
// Prep B: W[k][n] -> g_Wt[w][n][k], tf32-rounded (32x32 smem transpose).
// ---------------------------------------------------------------------------
__global__ __launch_bounds__(256) void wt_kernel(
    const float* __restrict__ Wq, const float* __restrict__ Wk,
    const float* __restrict__ Wv)
{
    __shared__ float t[32][33];
    const int w = blockIdx.z;
    const float* W = (w == 0) ? Wq : ((w == 1) ? Wk : Wv);
    const int k0 = blockIdx.x * 32, n0 = blockIdx.y * 32;
    const int lane = threadIdx.x & 31, warp = threadIdx.x >> 5;
#pragma unroll
    for (int i = 0; i < 4; i++) {
        const int ky = warp + i * 8;
        t[ky][lane] = ftf32(W[(size_t)(k0 + ky) * HID + n0 + lane]);
    }
    __syncthreads();
#pragma unroll
    for (int i = 0; i < 4; i++) {
        const int nr = warp * 4 + i;
        g_Wt[((size_t)w * HID + n0 + nr) * C + k0 + lane] = t[lane][nr];
    }
}

// ---------------------------------------------------------------------------
// Kernel 1: QKV projection. tf32 mma.sync + full cp.async 3-stage pipeline +
// ldmatrix fragments. Block 128(M)x256(N), BK=32, 8 warps (2m x 4n), warp 64x64.
// Smem per stage: A 16KB ([m][k] rows swizzled) + B 32KB ([n][k] rows swizzled).
// ---------------------------------------------------------------------------
#define STAGE_BYTES 49152
__global__ __launch_bounds__(256) void qkv_mma_kernel(
    const float* __restrict__ bq, const float* __restrict__ bk,
    const float* __restrict__ bv)
{
    extern __shared__ float smem[];
    const uint32_t s0 = smem_u32(smem);

    const int tid  = threadIdx.x;
    const int lane = tid & 31;
    const int warp = tid >> 5;
    const int wm   = warp & 1;
    const int wn   = warp >> 1;
    const int gr   = lane >> 2;
    const int gc   = lane & 3;

    const int by = blockIdx.x;      // 0..11
    const int bm = blockIdx.y;      // 0..511
    const int w  = by >> 2;
    const int colbase = (by & 3) * 256;

    // ldmatrix per-thread constants: unit = lane>>3
    const int unit = lane >> 3;
    const int u2   = unit >> 1;                 // 0: k, 1: k+4
    const int urow = ((unit & 1) << 3) | (lane & 7);
    const uint32_t uoff = (uint32_t)urow * 128;
    const int rp = lane & 7;                    // row & 7 within 16-row tile

    // cp.async mappings (row*256 src stride, row*128B dst rows, XOR swizzle)
    const float* aSrc = g_Xr + (size_t)(bm * 128) * C;
    const float* bSrc = g_Wt + ((size_t)w * HID + colbase) * C;
    int asrco[4]; uint32_t adsto[4];
#pragma unroll
    for (int i = 0; i < 4; i++) {
        const int c = i * 256 + tid, row = c >> 3, g = c & 7;
        asrco[i] = row * C + g * 4;
        adsto[i] = (uint32_t)(row * 128 + ((g ^ (row & 7)) << 4));
    }
    int bsrco[8]; uint32_t bdsto[8];
#pragma unroll
    for (int i = 0; i < 8; i++) {
        const int c = i * 256 + tid, row = c >> 3, g = c & 7;
        bsrco[i] = row * C + g * 4;
        bdsto[i] = (uint32_t)(16384 + row * 128 + ((g ^ (row & 7)) << 4));
    }

    float acc[4][8][4];
#pragma unroll
    for (int mf = 0; mf < 4; mf++)
#pragma unroll
        for (int nf = 0; nf < 8; nf++)
#pragma unroll
            for (int i = 0; i < 4; i++) acc[mf][nf][i] = 0.f;

#define ISSUE_STAGE(kt)                                                       \
    {                                                                         \
        const uint32_t sb = s0 + ((kt) % 3) * STAGE_BYTES;                    \
        const int kf = (kt) * 32;                                             \
        _Pragma("unroll")                                                     \
        for (int i = 0; i < 4; i++) cp16(sb + adsto[i], aSrc + kf + asrco[i]);\
        _Pragma("unroll")                                                     \
        for (int i = 0; i < 8; i++) cp16(sb + bdsto[i], bSrc + kf + bsrco[i]);\
    }

    // prologue: stages 0, 1
    ISSUE_STAGE(0) cp_commit();
    ISSUE_STAGE(1) cp_commit();

    for (int kt = 0; kt < 8; kt++) {
        cp_wait<1>();            // stage kt complete (groups: kt in G_kt, committed G0..G_{kt+1})
        __syncthreads();         // all warps done with stage kt-1's buffer
        if (kt + 2 < 8) ISSUE_STAGE(kt + 2)
        cp_commit();             // uniform group counting (empty near the end)

        const uint32_t sA  = s0 + (kt % 3) * STAGE_BYTES;
        const uint32_t sBv = sA + 16384;
#pragma unroll
        for (int ks = 0; ks < 4; ks++) {
            const uint32_t kswz = (uint32_t)((((ks * 2 + u2) ^ rp) & 7) << 4);
            uint32_t afr[4][4];
#pragma unroll
            for (int mf = 0; mf < 4; mf++)
                ldsm4(afr[mf][0], afr[mf][1], afr[mf][2], afr[mf][3],
                      sA + (uint32_t)(wm * 8192 + mf * 2048) + uoff + kswz);
            uint32_t b0v[8], b1v[8];
#pragma unroll
            for (int nfp = 0; nfp < 4; nfp++)
                ldsm4(b0v[2 * nfp], b0v[2 * nfp + 1], b1v[2 * nfp], b1v[2 * nfp + 1],
                      sBv + (uint32_t)(wn * 8192 + nfp * 2048) + uoff + kswz);
#pragma unroll
            for (int nf = 0; nf < 8; nf++)
#pragma unroll
                for (int mf = 0; mf < 4; mf++)
                    mma_tf32(acc[mf][nf], afr[mf], b0v[nf], b1v[nf]);
        }
    }

    // Epilogue: bias + feature map
    const float* bias = (w == 0) ? bq : ((w == 1) ? bk : bv);
    float* OUT        = (w == 0) ? g_Q : ((w == 1) ? g_K : g_V);
    const bool fmap = (w < 2);
#pragma unroll
    for (int mf = 0; mf < 4; mf++) {
        const int mrow = bm * 128 + wm * 64 + mf * 16 + gr;
#pragma unroll
        for (int nf = 0; nf < 8; nf++) {
            const int col = colbase + wn * 64 + nf * 8 + 2 * gc;
            const float b0v = bias[col];
            const float b1v = bias[col + 1];
            float v0 = acc[mf][nf][0] + b0v;
            float v1 = acc[mf][nf][1] + b1v;
            float v2 = acc[mf][nf][2] + b0v;
            float v3 = acc[mf][nf][3] + b1v;
            if (fmap) {
                v0 = (v0 > 0.f) ? (v0 + 1.f) : __expf(v0);
                v1 = (v1 > 0.f) ? (v1 + 1.f) : __expf(v1);
                v2 = (v2 > 0.f) ? (v2 + 1.f) : __expf(v2);
                v3 = (v3 > 0.f) ? (v3 + 1.f) : __expf(v3);
            }
            *(float2*)&OUT[(size_t)mrow * HID + col]       = make_float2(v0, v1);
            *(float2*)&OUT[(size_t)(mrow + 8) * HID + col] = make_float2(v2, v3);
        }
    }
}

// ===================== kv / out kernels (R3, proven) =========================
#define MMA_TILE_BODY(As, Bs, acc)                                            \
    _Pragma("unroll")                                                         \
    for (int ks = 0; ks < 4; ks++) {                                          \
        const int kk = ks * 8;                                                \
        uint32_t afr[2][4];                                                   \
        _Pragma("unroll")                                                     \
        for (int mf = 0; mf < 2; mf++) {                                      \
            const int m0 = wm2 * 32 + mf * 16;                                \
            afr[mf][0] = __float_as_uint(As[kk + gc][m0 + gr]);               \
            afr[mf][1] = __float_as_uint(As[kk + gc][m0 + gr + 8]);           \
            afr[mf][2] = __float_as_uint(As[kk + gc + 4][m0 + gr]);           \
            afr[mf][3] = __float_as_uint(As[kk + gc + 4][m0 + gr + 8]);       \
        }                                                                     \
        _Pragma("unroll")                                                     \
        for (int nf = 0; nf < 8; nf++) {                                      \
            const int n0 = wn2 * 64 + nf * 8;                                 \
            const uint32_t b0 = __float_as_uint(Bs[kk + gc][n0 + gr]);        \
            const uint32_t b1 = __float_as_uint(Bs[kk + gc + 4][n0 + gr]);    \
            mma_tf32(acc[0][nf], afr[0], b0, b1);                             \
            mma_tf32(acc[1][nf], afr[1], b0, b1);                             \
        }                                                                     \
    }

__global__ __launch_bounds__(256) void kv_mma_kernel()
{
    __shared__ float As[32][136];
    __shared__ float Bs[32][136];
    __shared__ float sKsum[128];

    const int tid  = threadIdx.x;
    const int lane = tid & 31;
    const int warp = tid >> 5;
    const int wm2  = warp & 3;
    const int wn2  = warp >> 2;
    const int gr   = lane >> 2;
    const int gc   = lane & 3;

    const int n = blockIdx.x, h = blockIdx.y;
    const size_t base = (size_t)n * F * HID + (size_t)h * D;

    const int sr = tid >> 3;
    const int c0 = (tid & 7) * 4;
    const float* vptr = g_V + base + (size_t)sr * HID + c0;
    const float* kptr = g_K + base + (size_t)sr * HID + c0;

    if (tid < 128) sKsum[tid] = 0.f;
    float4 kacc[4];
#pragma unroll
    for (int i = 0; i < 4; i++) kacc[i] = make_float4(0.f, 0.f, 0.f, 0.f);

    float acc[2][8][4];
#pragma unroll
    for (int mf = 0; mf < 2; mf++)
#pragma unroll
        for (int nf = 0; nf < 8; nf++)
#pragma unroll
            for (int i = 0; i < 4; i++) acc[mf][nf][i] = 0.f;

    for (int s0 = 0; s0 < F; s0 += 32) {
        float4 av[4], ak[4];
#pragma unroll
        for (int i = 0; i < 4; i++) {
            av[i] = *(const float4*)(vptr + (size_t)s0 * HID + i * 32);
            ak[i] = *(const float4*)(kptr + (size_t)s0 * HID + i * 32);
        }
        __syncthreads();
#pragma unroll
        for (int i = 0; i < 4; i++) {
            float4 tv = av[i], tk = ak[i];
            kacc[i].x += tk.x; kacc[i].y += tk.y; kacc[i].z += tk.z; kacc[i].w += tk.w;
            tv.x = ftf32(tv.x); tv.y = ftf32(tv.y); tv.z = ftf32(tv.z); tv.w = ftf32(tv.w);
            tk.x = ftf32(tk.x); tk.y = ftf32(tk.y); tk.z = ftf32(tk.z); tk.w = ftf32(tk.w);
            *(float4*)&As[sr][c0 + i * 32] = tv;
            *(float4*)&Bs[sr][c0 + i * 32] = tk;
        }
        __syncthreads();

        MMA_TILE_BODY(As, Bs, acc)
    }

#pragma unroll
    for (int i = 0; i < 4; i++) {
        atomicAdd(&sKsum[c0 + i * 32 + 0], kacc[i].x);
        atomicAdd(&sKsum[c0 + i * 32 + 1], kacc[i].y);
        atomicAdd(&sKsum[c0 + i * 32 + 2], kacc[i].z);
        atomicAdd(&sKsum[c0 + i * 32 + 3], kacc[i].w);
    }
    __syncthreads();

    const size_t nh = (size_t)n * H + h;
    if (tid < 128) g_Ksum[nh * D + tid] = sKsum[tid];

    const size_t kvbase = nh * D * D;
#pragma unroll
    for (int mf = 0; mf < 2; mf++) {
        const int mrow = wm2 * 32 + mf * 16 + gr;
#pragma unroll
        for (int nf = 0; nf < 8; nf++) {
            const int ncol = wn2 * 64 + nf * 8 + 2 * gc;
            *(float2*)&g_KV[kvbase + (size_t)mrow * D + ncol] =
                make_float2(acc[mf][nf][0], acc[mf][nf][1]);
            *(float2*)&g_KV[kvbase + (size_t)(mrow + 8) * D + ncol] =
                make_float2(acc[mf][nf][2], acc[mf][nf][3]);
        }
    }
}

__global__ __launch_bounds__(256) void out_mma_kernel(float* __restrict__ out)
{
    __shared__ float As[32][136];
    __shared__ float Bs[32][136];
    __shared__ float sZ[128];
    __shared__ float sKs[128];

    const int tid  = threadIdx.x;
    const int lane = tid & 31;
    const int warp = tid >> 5;
    const int wm2  = warp & 3;
    const int wn2  = warp >> 2;
    const int gr   = lane >> 2;
    const int gc   = lane & 3;

    const int lt = blockIdx.x, n = blockIdx.y, h = blockIdx.z;
    const int l0 = lt * 128;
    const size_t nh = (size_t)n * H + h;
    const size_t qbase  = ((size_t)n * F + l0) * HID + (size_t)h * D;
    const size_t kvbase = nh * D * D;

    if (tid < 128) sKs[tid] = g_Ksum[nh * D + tid];
    __syncthreads();

    {
        float4 kv4 = *(const float4*)&sKs[lane * 4];
#pragma unroll
        for (int r8 = 0; r8 < 16; r8++) {
            const int row = warp * 16 + r8;
            const float* q = g_Q + qbase + (size_t)row * HID;
            float4 qv = *(const float4*)(q + lane * 4);
            float d = qv.x * kv4.x + qv.y * kv4.y + qv.z * kv4.z + qv.w * kv4.w;
#pragma unroll
            for (int off = 16; off; off >>= 1) d += __shfl_xor_sync(0xffffffffu, d, off);
            if (lane == 0) sZ[row] = 1.f / (d + EPSV);
        }
    }

    const int lr  = tid >> 1;
    const int d16 = (tid & 1) * 16;
    const float* qp  = g_Q + qbase + (size_t)lr * HID + d16;
    const float* kvp = g_KV + kvbase + (size_t)lr * D + d16;

    float acc[2][8][4];
#pragma unroll
    for (int mf = 0; mf < 2; mf++)
#pragma unroll
        for (int nf = 0; nf < 8; nf++)
#pragma unroll
            for (int i = 0; i < 4; i++) acc[mf][nf][i] = 0.f;

    for (int d0 = 0; d0 < D; d0 += 32) {
        float4 aR[4], bR[4];
#pragma unroll
        for (int i = 0; i < 4; i++) {
            aR[i] = *(const float4*)(qp + d0 + i * 4);
            bR[i] = *(const float4*)(kvp + d0 + i * 4);
        }
        __syncthreads();
#pragma unroll
        for (int i = 0; i < 4; i++) {
            const int kb = d16 + i * 4;
            As[kb + 0][lr] = ftf32(aR[i].x);
            As[kb + 1][lr] = ftf32(aR[i].y);
            As[kb + 2][lr] = ftf32(aR[i].z);
            As[kb + 3][lr] = ftf32(aR[i].w);
            Bs[kb + 0][lr] = ftf32(bR[i].x);
            Bs[kb + 1][lr] = ftf32(bR[i].y);
            Bs[kb + 2][lr] = ftf32(bR[i].z);
            Bs[kb + 3][lr] = ftf32(bR[i].w);
        }
        __syncthreads();

        MMA_TILE_BODY(As, Bs, acc)
    }

#pragma unroll
    for (int mf = 0; mf < 2; mf++) {
        const int row = wm2 * 32 + mf * 16 + gr;
        const float z0 = sZ[row];
        const float z1 = sZ[row + 8];
        const size_t ob0 = (size_t)(l0 + row) * (NJ * HID) + (size_t)n * HID + (size_t)h * D;
        const size_t ob1 = (size_t)(l0 + row + 8) * (NJ * HID) + (size_t)n * HID + (size_t)h * D;
#pragma unroll
        for (int nf = 0; nf < 8; nf++) {
            const int ncol = wn2 * 64 + nf * 8 + 2 * gc;
            *(float2*)&out[ob0 + ncol] =
                make_float2(acc[mf][nf][0] * z0, acc[mf][nf][1] * z0);
            *(float2*)&out[ob1 + ncol] =
                make_float2(acc[mf][nf][2] * z1, acc[mf][nf][3] * z1);
        }
    }
}

// ---------------------------------------------------------------------------
extern "C" void kernel_launch(void* const* d_in, const int* in_sizes, int n_in,
                              void* d_out, int out_size)
{
    const float* x  = (const float*)d_in[0];
    const float* Wq = (const float*)d_in[1];
    const float* bq = (const float*)d_in[2];
    const float* Wk = (const float*)d_in[3];
    const float* bk = (const float*)d_in[4];
    const float* Wv = (const float*)d_in[5];
    const float* bv = (const float*)d_in[6];
    float* out = (float*)d_out;

    // Prep: tf32-rounded staging images
    xr_kernel<<<M_TOT / 8, 256>>>(x);
    dim3 gw(C / 32, HID / 32, 3);
    wt_kernel<<<gw, 256>>>(Wq, Wk, Wv);

    // QKV: 3-stage cp.async + ldmatrix pipeline
    const int smem1 = 3 * STAGE_BYTES;   // 147456 B
    cudaFuncSetAttribute(qkv_mma_kernel,
                         cudaFuncAttributeMaxDynamicSharedMemorySize, smem1);
    dim3 g1(12, M_TOT / 128);
    qkv_mma_kernel<<<g1, 256, smem1>>>(bq, bk, bv);

    dim3 g2(NJ, H);
    kv_mma_kernel<<<g2, 256>>>();

    dim3 g3(F / 128, NJ, H);
    out_mma_kernel<<<g3, 256>>>(out);
}

// round 10
// speedup vs baseline: 1.1461x; 1.0441x over previous
#include <cuda_runtime.h>
#include <math.h>
#include <stdint.h>

#define F    1024
#define NJ   64
#define C    256
#define HID  1024
#define H    8
#define D    128
#define M_TOT (NJ * F)      // 65536
#define EPSV 1e-6f

// Scratch (device globals — no allocation allowed in kernel_launch)
__device__ float g_Q[(size_t)M_TOT * HID];      // tf32-rounded, feature-mapped
__device__ float g_K[(size_t)M_TOT * HID];      // tf32-rounded, feature-mapped
__device__ float g_V[(size_t)M_TOT * HID];      // tf32-rounded
__device__ float g_KV[(size_t)NJ * H * D * D];  // [n,h,m,d], tf32-rounded
__device__ float g_Ksum[(size_t)NJ * H * D];
__device__ float g_Xr[(size_t)M_TOT * C];       // x as [m][k], tf32-rounded
__device__ float g_Wt[(size_t)3 * HID * C];     // W as [w][n][k], tf32-rounded

__device__ __forceinline__ float ftf32(float x) {
    float r;
    asm("cvt.rna.tf32.f32 %0, %1;" : "=f"(r) : "f"(x));
    return r;
}

__device__ __forceinline__ uint32_t smem_u32(const void* p) {
    uint32_t a;
    asm("{ .reg .u64 t; cvta.to.shared.u64 t, %1; cvt.u32.u64 %0, t; }"
        : "=r"(a) : "l"(p));
    return a;
}

__device__ __forceinline__ void cp16(uint32_t dst_smem, const void* src) {
    asm volatile("cp.async.cg.shared.global [%0], [%1], 16;"
                 :: "r"(dst_smem), "l"(__cvta_generic_to_global(src)) : "memory");
}
__device__ __forceinline__ void cp_commit() {
    asm volatile("cp.async.commit_group;" ::: "memory");
}
template <int N>
__device__ __forceinline__ void cp_wait() {
    asm volatile("cp.async.wait_group %0;" :: "n"(N) : "memory");
}

__device__ __forceinline__ void mma_tf32(float* c, const uint32_t* a,
                                         uint32_t b0, uint32_t b1) {
    asm volatile(
        "mma.sync.aligned.m16n8k8.row.col.f32.tf32.tf32.f32 "
        "{%0,%1,%2,%3}, {%4,%5,%6,%7}, {%8,%9}, {%0,%1,%2,%3};"
        : "+f"(c[0]), "+f"(c[1]), "+f"(c[2]), "+f"(c[3])
        : "r"(a[0]), "r"(a[1]), "r"(a[2]), "r"(a[3]), "r"(b0), "r"(b1));
}

__device__ __forceinline__ void ldsm4(uint32_t& r0, uint32_t& r1,
                                      uint32_t& r2, uint32_t& r3, uint32_t addr) {
    asm volatile("ldmatrix.sync.aligned.m8n8.x4.shared.b16 {%0,%1,%2,%3}, [%4];"
                 : "=r"(r0), "=r"(r1), "=r"(r2), "=r"(r3) : "r"(addr));
}

// ---------------------------------------------------------------------------
// Prep A: x[f][n][c] -> g_Xr[m][k] (m = n*F+f), tf32-rounded.
// ---------------------------------------------------------------------------
__global__ __launch_bounds__(256) void xr_kernel(const float* __restrict__ x)
{
    const int warp = threadIdx.x >> 5, lane = threadIdx.x & 31;
    const int m = blockIdx.x * 8 + warp;
    const int f = m & (F - 1), n = m >> 10;
    const float* src = x + ((size_t)f * NJ + n) * C + lane * 8;
    float* dst = g_Xr + (size_t)m * C + lane * 8;
    float4 v0 = *(const float4*)(src);
    float4 v1 = *(const float4*)(src + 4);
    v0.x = ftf32(v0.x); v0.y = ftf32(v0.y); v0.z = ftf32(v0.z); v0.w = ftf32(v0.w);
    v1.x = ftf32(v1.x); v1.y = ftf32(v1.y); v1.z = ftf32(v1.z); v1.w = ftf32(v1.w);
    *(float4*)(dst)     = v0;
    *(float4*)(dst + 4) = v1;
}

// ---------------------------------------------------------------------------
// Prep B: W[k][n] -> g_Wt[w][n][k], tf32-rounded (32x32 smem transpose).
// ---------------------------------------------------------------------------
__global__ __launch_bounds__(256) void wt_kernel(
    const float* __restrict__ Wq, const float* __restrict__ Wk,
    const float* __restrict__ Wv)
{
    __shared__ float t[32][33];
    const int w = blockIdx.z;
    const float* W = (w == 0) ? Wq : ((w == 1) ? Wk : Wv);
    const int k0 = blockIdx.x * 32, n0 = blockIdx.y * 32;
    const int lane = threadIdx.x & 31, warp = threadIdx.x >> 5;
#pragma unroll
    for (int i = 0; i < 4; i++) {
        const int ky = warp + i * 8;
        t[ky][lane] = ftf32(W[(size_t)(k0 + ky) * HID + n0 + lane]);
    }
    __syncthreads();
#pragma unroll
    for (int i = 0; i < 4; i++) {
        const int nr = warp * 4 + i;
        g_Wt[((size_t)w * HID + n0 + nr) * C + k0 + lane] = t[lane][nr];
    }
}

// ---------------------------------------------------------------------------
// Kernel 1: QKV projection (R9 pipeline). Outputs stored tf32-rounded.
// ---------------------------------------------------------------------------
#define STAGE_BYTES 49152
__global__ __launch_bounds__(256) void qkv_mma_kernel(
    const float* __restrict__ bq, const float* __restrict__ bk,
    const float* __restrict__ bv)
{
    extern __shared__ float smem[];
    const uint32_t s0 = smem_u32(smem);

    const int tid  = threadIdx.x;
    const int lane = tid & 31;
    const int warp = tid >> 5;
    const int wm   = warp & 1;
    const int wn   = warp >> 1;
    const int gr   = lane >> 2;
    const int gc   = lane & 3;

    const int by = blockIdx.x;      // 0..11
    const int bm = blockIdx.y;      // 0..511
    const int w  = by >> 2;
    const int colbase = (by & 3) * 256;

    const int unit = lane >> 3;
    const int u2   = unit >> 1;
    const int urow = ((unit & 1) << 3) | (lane & 7);
    const uint32_t uoff = (uint32_t)urow * 128;
    const int rp = lane & 7;

    const float* aSrc = g_Xr + (size_t)(bm * 128) * C;
    const float* bSrc = g_Wt + ((size_t)w * HID + colbase) * C;
    int asrco[4]; uint32_t adsto[4];
#pragma unroll
    for (int i = 0; i < 4; i++) {
        const int c = i * 256 + tid, row = c >> 3, g = c & 7;
        asrco[i] = row * C + g * 4;
        adsto[i] = (uint32_t)(row * 128 + ((g ^ (row & 7)) << 4));
    }
    int bsrco[8]; uint32_t bdsto[8];
#pragma unroll
    for (int i = 0; i < 8; i++) {
        const int c = i * 256 + tid, row = c >> 3, g = c & 7;
        bsrco[i] = row * C + g * 4;
        bdsto[i] = (uint32_t)(16384 + row * 128 + ((g ^ (row & 7)) << 4));
    }

    float acc[4][8][4];
#pragma unroll
    for (int mf = 0; mf < 4; mf++)
#pragma unroll
        for (int nf = 0; nf < 8; nf++)
#pragma unroll
            for (int i = 0; i < 4; i++) acc[mf][nf][i] = 0.f;

#define ISSUE_STAGE(kt)                                                       \
    {                                                                         \
        const uint32_t sb = s0 + ((kt) % 3) * STAGE_BYTES;                    \
        const int kf = (kt) * 32;                                             \
        _Pragma("unroll")                                                     \
        for (int i = 0; i < 4; i++) cp16(sb + adsto[i], aSrc + kf + asrco[i]);\
        _Pragma("unroll")                                                     \
        for (int i = 0; i < 8; i++) cp16(sb + bdsto[i], bSrc + kf + bsrco[i]);\
    }

    ISSUE_STAGE(0) cp_commit();
    ISSUE_STAGE(1) cp_commit();

    for (int kt = 0; kt < 8; kt++) {
        cp_wait<1>();
        __syncthreads();
        if (kt + 2 < 8) ISSUE_STAGE(kt + 2)
        cp_commit();

        const uint32_t sA  = s0 + (kt % 3) * STAGE_BYTES;
        const uint32_t sBv = sA + 16384;
#pragma unroll
        for (int ks = 0; ks < 4; ks++) {
            const uint32_t kswz = (uint32_t)((((ks * 2 + u2) ^ rp) & 7) << 4);
            uint32_t afr[4][4];
#pragma unroll
            for (int mf = 0; mf < 4; mf++)
                ldsm4(afr[mf][0], afr[mf][1], afr[mf][2], afr[mf][3],
                      sA + (uint32_t)(wm * 8192 + mf * 2048) + uoff + kswz);
            uint32_t b0v[8], b1v[8];
#pragma unroll
            for (int nfp = 0; nfp < 4; nfp++)
                ldsm4(b0v[2 * nfp], b0v[2 * nfp + 1], b1v[2 * nfp], b1v[2 * nfp + 1],
                      sBv + (uint32_t)(wn * 8192 + nfp * 2048) + uoff + kswz);
#pragma unroll
            for (int nf = 0; nf < 8; nf++)
#pragma unroll
                for (int mf = 0; mf < 4; mf++)
                    mma_tf32(acc[mf][nf], afr[mf], b0v[nf], b1v[nf]);
        }
    }

    // Epilogue: bias + feature map + tf32 rounding (consumers use pre-rounded data)
    const float* bias = (w == 0) ? bq : ((w == 1) ? bk : bv);
    float* OUT        = (w == 0) ? g_Q : ((w == 1) ? g_K : g_V);
    const bool fmap = (w < 2);
#pragma unroll
    for (int mf = 0; mf < 4; mf++) {
        const int mrow = bm * 128 + wm * 64 + mf * 16 + gr;
#pragma unroll
        for (int nf = 0; nf < 8; nf++) {
            const int col = colbase + wn * 64 + nf * 8 + 2 * gc;
            const float b0v = bias[col];
            const float b1v = bias[col + 1];
            float v0 = acc[mf][nf][0] + b0v;
            float v1 = acc[mf][nf][1] + b1v;
            float v2 = acc[mf][nf][2] + b0v;
            float v3 = acc[mf][nf][3] + b1v;
            if (fmap) {
                v0 = (v0 > 0.f) ? (v0 + 1.f) : __expf(v0);
                v1 = (v1 > 0.f) ? (v1 + 1.f) : __expf(v1);
                v2 = (v2 > 0.f) ? (v2 + 1.f) : __expf(v2);
                v3 = (v3 > 0.f) ? (v3 + 1.f) : __expf(v3);
            }
            v0 = ftf32(v0); v1 = ftf32(v1); v2 = ftf32(v2); v3 = ftf32(v3);
            *(float2*)&OUT[(size_t)mrow * HID + col]       = make_float2(v0, v1);
            *(float2*)&OUT[(size_t)(mrow + 8) * HID + col] = make_float2(v2, v3);
        }
    }
}

// ===================== kv kernel (inputs pre-rounded; KV stored rounded) =====
#define MMA_TILE_BODY(As, Bs, acc)                                            \
    _Pragma("unroll")                                                         \
    for (int ks = 0; ks < 4; ks++) {                                          \
        const int kk = ks * 8;                                                \
        uint32_t afr[2][4];                                                   \
        _Pragma("unroll")                                                     \
        for (int mf = 0; mf < 2; mf++) {                                      \
            const int m0 = wm2 * 32 + mf * 16;                                \
            afr[mf][0] = __float_as_uint(As[kk + gc][m0 + gr]);               \
            afr[mf][1] = __float_as_uint(As[kk + gc][m0 + gr + 8]);           \
            afr[mf][2] = __float_as_uint(As[kk + gc + 4][m0 + gr]);           \
            afr[mf][3] = __float_as_uint(As[kk + gc + 4][m0 + gr + 8]);       \
        }                                                                     \
        _Pragma("unroll")                                                     \
        for (int nf = 0; nf < 8; nf++) {                                      \
            const int n0 = wn2 * 64 + nf * 8;                                 \
            const uint32_t b0 = __float_as_uint(Bs[kk + gc][n0 + gr]);        \
            const uint32_t b1 = __float_as_uint(Bs[kk + gc + 4][n0 + gr]);    \
            mma_tf32(acc[0][nf], afr[0], b0, b1);                             \
            mma_tf32(acc[1][nf], afr[1], b0, b1);                             \
        }                                                                     \
    }

__global__ __launch_bounds__(256) void kv_mma_kernel()
{
    __shared__ float As[32][136];
    __shared__ float Bs[32][136];
    __shared__ float sKsum[128];

    const int tid  = threadIdx.x;
    const int lane = tid & 31;
    const int warp = tid >> 5;
    const int wm2  = warp & 3;
    const int wn2  = warp >> 2;
    const int gr   = lane >> 2;
    const int gc   = lane & 3;

    const int n = blockIdx.x, h = blockIdx.y;
    const size_t base = (size_t)n * F * HID + (size_t)h * D;

    const int sr = tid >> 3;
    const int c0 = (tid & 7) * 4;
    const float* vptr = g_V + base + (size_t)sr * HID + c0;
    const float* kptr = g_K + base + (size_t)sr * HID + c0;

    if (tid < 128) sKsum[tid] = 0.f;
    float4 kacc[4];
#pragma unroll
    for (int i = 0; i < 4; i++) kacc[i] = make_float4(0.f, 0.f, 0.f, 0.f);

    float acc[2][8][4];
#pragma unroll
    for (int mf = 0; mf < 2; mf++)
#pragma unroll
        for (int nf = 0; nf < 8; nf++)
#pragma unroll
            for (int i = 0; i < 4; i++) acc[mf][nf][i] = 0.f;

    for (int s0 = 0; s0 < F; s0 += 32) {
        float4 av[4], ak[4];
#pragma unroll
        for (int i = 0; i < 4; i++) {
            av[i] = *(const float4*)(vptr + (size_t)s0 * HID + i * 32);
            ak[i] = *(const float4*)(kptr + (size_t)s0 * HID + i * 32);
        }
        __syncthreads();
#pragma unroll
        for (int i = 0; i < 4; i++) {
            kacc[i].x += ak[i].x; kacc[i].y += ak[i].y;
            kacc[i].z += ak[i].z; kacc[i].w += ak[i].w;
            *(float4*)&As[sr][c0 + i * 32] = av[i];
            *(float4*)&Bs[sr][c0 + i * 32] = ak[i];
        }
        __syncthreads();

        MMA_TILE_BODY(As, Bs, acc)
    }

#pragma unroll
    for (int i = 0; i < 4; i++) {
        atomicAdd(&sKsum[c0 + i * 32 + 0], kacc[i].x);
        atomicAdd(&sKsum[c0 + i * 32 + 1], kacc[i].y);
        atomicAdd(&sKsum[c0 + i * 32 + 2], kacc[i].z);
        atomicAdd(&sKsum[c0 + i * 32 + 3], kacc[i].w);
    }
    __syncthreads();

    const size_t nh = (size_t)n * H + h;
    if (tid < 128) g_Ksum[nh * D + tid] = sKsum[tid];

    const size_t kvbase = nh * D * D;
#pragma unroll
    for (int mf = 0; mf < 2; mf++) {
        const int mrow = wm2 * 32 + mf * 16 + gr;
#pragma unroll
        for (int nf = 0; nf < 8; nf++) {
            const int ncol = wn2 * 64 + nf * 8 + 2 * gc;
            *(float2*)&g_KV[kvbase + (size_t)mrow * D + ncol] =
                make_float2(ftf32(acc[mf][nf][0]), ftf32(acc[mf][nf][1]));
            *(float2*)&g_KV[kvbase + (size_t)(mrow + 8) * D + ncol] =
                make_float2(ftf32(acc[mf][nf][2]), ftf32(acc[mf][nf][3]));
        }
    }
}

// ---------------------------------------------------------------------------
// Kernel 3: out = Z * (Q @ KV^T). cp.async 3-stage + ldmatrix pipeline.
// Block 128(l) x 128(m), 8 warps (2l x 4m), warp tile 64x32. K = D = 128.
// ---------------------------------------------------------------------------
#define OSTAGE 32768
__global__ __launch_bounds__(256) void out_mma_kernel(float* __restrict__ out)
{
    extern __shared__ float osm[];
    __shared__ float sZ[128];
    __shared__ float sKs[128];
    const uint32_t s0 = smem_u32(osm);

    const int tid  = threadIdx.x;
    const int lane = tid & 31;
    const int warp = tid >> 5;
    const int wm   = warp & 1;      // l offset wm*64
    const int wn   = warp >> 1;     // m offset wn*32
    const int gr   = lane >> 2;
    const int gc   = lane & 3;

    const int lt = blockIdx.x;      // 0..7
    const int n = blockIdx.y, h = blockIdx.z;
    const int l0 = lt * 128;
    const size_t nh = (size_t)n * H + h;
    const size_t qbase  = ((size_t)n * F + l0) * HID + (size_t)h * D;
    const size_t kvbase = nh * (size_t)D * D;

    const int unit = lane >> 3;
    const int u2   = unit >> 1;
    const int urow = ((unit & 1) << 3) | (lane & 7);
    const uint32_t uoff = (uint32_t)urow * 128;
    const int rp = lane & 7;

    // cp.async mappings: A rows stride HID, B rows stride D; dst 128B rows XOR-swz
    const float* aSrc = g_Q + qbase;
    const float* bSrc = g_KV + kvbase;
    int asrco[4]; int bsrco[4]; uint32_t adsto[4], bdsto[4];
#pragma unroll
    for (int i = 0; i < 4; i++) {
        const int c = i * 256 + tid, row = c >> 3, g = c & 7;
        asrco[i] = row * HID + g * 4;
        bsrco[i] = row * D + g * 4;
        adsto[i] = (uint32_t)(row * 128 + ((g ^ (row & 7)) << 4));
        bdsto[i] = (uint32_t)(16384 + row * 128 + ((g ^ (row & 7)) << 4));
    }

#define O_ISSUE(kt)                                                           \
    {                                                                         \
        const uint32_t sb = s0 + ((kt) % 3) * OSTAGE;                         \
        const int kf = (kt) * 32;                                             \
        _Pragma("unroll")                                                     \
        for (int i = 0; i < 4; i++) {                                         \
            cp16(sb + adsto[i], aSrc + kf + asrco[i]);                        \
            cp16(sb + bdsto[i], bSrc + kf + bsrco[i]);                        \
        }                                                                     \
    }

    O_ISSUE(0) cp_commit();
    O_ISSUE(1) cp_commit();

    // Z while copies fly: one warp per row group, coalesced float4 + shfl reduce
    if (tid < 128) sKs[tid] = g_Ksum[nh * D + tid];
    __syncwarp();
    {
        float4 kv4;
        {
            const float* ks = g_Ksum + nh * D;
            kv4 = *(const float4*)(ks + lane * 4);
        }
#pragma unroll
        for (int r8 = 0; r8 < 16; r8++) {
            const int row = warp * 16 + r8;
            const float* q = g_Q + qbase + (size_t)row * HID;
            float4 qv = *(const float4*)(q + lane * 4);
            float dd = qv.x * kv4.x + qv.y * kv4.y + qv.z * kv4.z + qv.w * kv4.w;
#pragma unroll
            for (int off = 16; off; off >>= 1) dd += __shfl_xor_sync(0xffffffffu, dd, off);
            if (lane == 0) sZ[row] = 1.f / (dd + EPSV);
        }
    }

    float acc[4][4][4];
#pragma unroll
    for (int mf = 0; mf < 4; mf++)
#pragma unroll
        for (int nf = 0; nf < 4; nf++)
#pragma unroll
            for (int i = 0; i < 4; i++) acc[mf][nf][i] = 0.f;

    for (int kt = 0; kt < 4; kt++) {
        cp_wait<1>();
        __syncthreads();
        if (kt + 2 < 4) O_ISSUE(kt + 2)
        cp_commit();

        const uint32_t sA  = s0 + (kt % 3) * OSTAGE;
        const uint32_t sBv = sA + 16384;
#pragma unroll
        for (int ks = 0; ks < 4; ks++) {
            const uint32_t kswz = (uint32_t)((((ks * 2 + u2) ^ rp) & 7) << 4);
            uint32_t afr[4][4];
#pragma unroll
            for (int mf = 0; mf < 4; mf++)
                ldsm4(afr[mf][0], afr[mf][1], afr[mf][2], afr[mf][3],
                      sA + (uint32_t)(wm * 8192 + mf * 2048) + uoff + kswz);
            uint32_t b0v[4], b1v[4];
#pragma unroll
            for (int nfp = 0; nfp < 2; nfp++)
                ldsm4(b0v[2 * nfp], b0v[2 * nfp + 1], b1v[2 * nfp], b1v[2 * nfp + 1],
                      sBv + (uint32_t)(wn * 4096 + nfp * 2048) + uoff + kswz);
#pragma unroll
            for (int nf = 0; nf < 4; nf++)
#pragma unroll
                for (int mf = 0; mf < 4; mf++)
                    mma_tf32(acc[mf][nf], afr[mf], b0v[nf], b1v[nf]);
        }
    }

    // Epilogue: scale by Z, store to out[f][n][h*D+m]
#pragma unroll
    for (int mf = 0; mf < 4; mf++) {
        const int row = wm * 64 + mf * 16 + gr;        // l within tile
        const float z0 = sZ[row];
        const float z1 = sZ[row + 8];
        const size_t ob0 = (size_t)(l0 + row) * (NJ * HID) + (size_t)n * HID + (size_t)h * D;
        const size_t ob1 = (size_t)(l0 + row + 8) * (NJ * HID) + (size_t)n * HID + (size_t)h * D;
#pragma unroll
        for (int nf = 0; nf < 4; nf++) {
            const int ncol = wn * 32 + nf * 8 + 2 * gc;
            *(float2*)&out[ob0 + ncol] =
                make_float2(acc[mf][nf][0] * z0, acc[mf][nf][1] * z0);
            *(float2*)&out[ob1 + ncol] =
                make_float2(acc[mf][nf][2] * z1, acc[mf][nf][3] * z1);
        }
    }
}

// ---------------------------------------------------------------------------
extern "C" void kernel_launch(void* const* d_in, const int* in_sizes, int n_in,
                              void* d_out, int out_size)
{
    const float* x  = (const float*)d_in[0];
    const float* Wq = (const float*)d_in[1];
    const float* bq = (const float*)d_in[2];
    const float* Wk = (const float*)d_in[3];
    const float* bk = (const float*)d_in[4];
    const float* Wv = (const float*)d_in[5];
    const float* bv = (const float*)d_in[6];
    float* out = (float*)d_out;

    xr_kernel<<<M_TOT / 8, 256>>>(x);
    dim3 gw(C / 32, HID / 32, 3);
    wt_kernel<<<gw, 256>>>(Wq, Wk, Wv);

    const int smem1 = 3 * STAGE_BYTES;   // 147456 B
    cudaFuncSetAttribute(qkv_mma_kernel,
                         cudaFuncAttributeMaxDynamicSharedMemorySize, smem1);
    dim3 g1(12, M_TOT / 128);
    qkv_mma_kernel<<<g1, 256, smem1>>>(bq, bk, bv);

    dim3 g2(NJ, H);
    kv_mma_kernel<<<g2, 256>>>();

    const int smem3 = 3 * OSTAGE;        // 98304 B
    cudaFuncSetAttribute(out_mma_kernel,
                         cudaFuncAttributeMaxDynamicSharedMemorySize, smem3);
    dim3 g3(F / 128, NJ, H);
    out_mma_kernel<<<g3, 256, smem3>>>(out);
}

// round 12
// speedup vs baseline: 1.1989x; 1.0461x over previous
#include <cuda_runtime.h>
#include <math.h>
#include <stdint.h>

#define F    1024
#define NJ   64
#define C    256
#define HID  1024
#define H    8
#define D    128
#define M_TOT (NJ * F)      // 65536
#define EPSV 1e-6f

// Scratch (device globals — no allocation allowed in kernel_launch)
__device__ float g_Q[(size_t)M_TOT * HID];      // tf32-rounded, feature-mapped
__device__ float g_K[(size_t)M_TOT * HID];      // tf32-rounded, feature-mapped
__device__ float g_V[(size_t)M_TOT * HID];      // tf32-rounded
__device__ float g_KV[(size_t)NJ * H * D * D];  // [n,h,m,d], tf32-rounded
__device__ float g_Ksum[(size_t)NJ * H * D];
__device__ float g_Xr[(size_t)M_TOT * C];       // x as [m][k], tf32-rounded
__device__ float g_Wt[(size_t)3 * HID * C];     // W as [w][n][k], tf32-rounded

__device__ __forceinline__ float ftf32(float x) {
    float r;
    asm("cvt.rna.tf32.f32 %0, %1;" : "=f"(r) : "f"(x));
    return r;
}

__device__ __forceinline__ uint32_t smem_u32(const void* p) {
    uint32_t a;
    asm("{ .reg .u64 t; cvta.to.shared.u64 t, %1; cvt.u32.u64 %0, t; }"
        : "=r"(a) : "l"(p));
    return a;
}

__device__ __forceinline__ void cp16(uint32_t dst_smem, const void* src) {
    asm volatile("cp.async.cg.shared.global [%0], [%1], 16;"
                 :: "r"(dst_smem), "l"(__cvta_generic_to_global(src)) : "memory");
}
__device__ __forceinline__ void cp_commit() {
    asm volatile("cp.async.commit_group;" ::: "memory");
}
template <int N>
__device__ __forceinline__ void cp_wait() {
    asm volatile("cp.async.wait_group %0;" :: "n"(N) : "memory");
}

__device__ __forceinline__ void mma_tf32(float* c, const uint32_t* a,
                                         uint32_t b0, uint32_t b1) {
    asm volatile(
        "mma.sync.aligned.m16n8k8.row.col.f32.tf32.tf32.f32 "
        "{%0,%1,%2,%3}, {%4,%5,%6,%7}, {%8,%9}, {%0,%1,%2,%3};"
        : "+f"(c[0]), "+f"(c[1]), "+f"(c[2]), "+f"(c[3])
        : "r"(a[0]), "r"(a[1]), "r"(a[2]), "r"(a[3]), "r"(b0), "r"(b1));
}

__device__ __forceinline__ void ldsm4(uint32_t& r0, uint32_t& r1,
                                      uint32_t& r2, uint32_t& r3, uint32_t addr) {
    asm volatile("ldmatrix.sync.aligned.m8n8.x4.shared.b16 {%0,%1,%2,%3}, [%4];"
                 : "=r"(r0), "=r"(r1), "=r"(r2), "=r"(r3) : "r"(addr));
}

// ---------------------------------------------------------------------------
// Prep A: x[f][n][c] -> g_Xr[m][k] (m = n*F+f), tf32-rounded.
// ---------------------------------------------------------------------------
__global__ __launch_bounds__(256) void xr_kernel(const float* __restrict__ x)
{
    const int warp = threadIdx.x >> 5, lane = threadIdx.x & 31;
    const int m = blockIdx.x * 8 + warp;
    const int f = m & (F - 1), n = m >> 10;
    const float* src = x + ((size_t)f * NJ + n) * C + lane * 8;
    float* dst = g_Xr + (size_t)m * C + lane * 8;
    float4 v0 = *(const float4*)(src);
    float4 v1 = *(const float4*)(src + 4);
    v0.x = ftf32(v0.x); v0.y = ftf32(v0.y); v0.z = ftf32(v0.z); v0.w = ftf32(v0.w);
    v1.x = ftf32(v1.x); v1.y = ftf32(v1.y); v1.z = ftf32(v1.z); v1.w = ftf32(v1.w);
    *(float4*)(dst)     = v0;
    *(float4*)(dst + 4) = v1;
}

// ---------------------------------------------------------------------------
// Prep B: W[k][n] -> g_Wt[w][n][k], tf32-rounded (32x32 smem transpose).
// ---------------------------------------------------------------------------
__global__ __launch_bounds__(256) void wt_kernel(
    const float* __restrict__ Wq, const float* __restrict__ Wk,
    const float* __restrict__ Wv)
{
    __shared__ float t[32][33];
    const int w = blockIdx.z;
    const float* W = (w == 0) ? Wq : ((w == 1) ? Wk : Wv);
    const int k0 = blockIdx.x * 32, n0 = blockIdx.y * 32;
    const int lane = threadIdx.x & 31, warp = threadIdx.x >> 5;
#pragma unroll
    for (int i = 0; i < 4; i++) {
        const int ky = warp + i * 8;
        t[ky][lane] = ftf32(W[(size_t)(k0 + ky) * HID + n0 + lane]);
    }
    __syncthreads();
#pragma unroll
    for (int i = 0; i < 4; i++) {
        const int nr = warp * 4 + i;
        g_Wt[((size_t)w * HID + n0 + nr) * C + k0 + lane] = t[lane][nr];
    }
}

// ---------------------------------------------------------------------------
// Kernel 1: QKV projection. 512 threads (16 warps, 4m x 4n), warp tile 32x64.
// Block 128(M)x256(N), BK=32, 3-stage cp.async + ldmatrix pipeline.
// Chunk math: A tile 128x32 fl = 16KB = 1024 chunks = 2/thread x 512 thr.
//             B tile 256x32 fl = 32KB = 2048 chunks = 4/thread x 512 thr.
// ---------------------------------------------------------------------------
#define STAGE_BYTES 49152
__global__ __launch_bounds__(512) void qkv_mma_kernel(
    const float* __restrict__ bq, const float* __restrict__ bk,
    const float* __restrict__ bv)
{
    extern __shared__ float smem[];
    const uint32_t s0 = smem_u32(smem);

    const int tid  = threadIdx.x;
    const int lane = tid & 31;
    const int warp = tid >> 5;
    const int wm   = warp & 3;      // m offset wm*32
    const int wn   = warp >> 2;     // n offset wn*64
    const int gr   = lane >> 2;
    const int gc   = lane & 3;

    const int by = blockIdx.x;      // 0..11
    const int bm = blockIdx.y;      // 0..511
    const int w  = by >> 2;
    const int colbase = (by & 3) * 256;

    const int unit = lane >> 3;
    const int u2   = unit >> 1;
    const int urow = ((unit & 1) << 3) | (lane & 7);
    const uint32_t uoff = (uint32_t)urow * 128;
    const int rp = lane & 7;

    const float* aSrc = g_Xr + (size_t)(bm * 128) * C;
    const float* bSrc = g_Wt + ((size_t)w * HID + colbase) * C;
    int asrco[2]; uint32_t adsto[2];
#pragma unroll
    for (int i = 0; i < 2; i++) {
        const int c = i * 512 + tid, row = c >> 3, g = c & 7;   // 128 rows x 8 granules
        asrco[i] = row * C + g * 4;
        adsto[i] = (uint32_t)(row * 128 + ((g ^ (row & 7)) << 4));
    }
    int bsrco[4]; uint32_t bdsto[4];
#pragma unroll
    for (int i = 0; i < 4; i++) {
        const int c = i * 512 + tid, row = c >> 3, g = c & 7;   // 256 rows x 8 granules
        bsrco[i] = row * C + g * 4;
        bdsto[i] = (uint32_t)(16384 + row * 128 + ((g ^ (row & 7)) << 4));
    }

    float acc[2][8][4];
#pragma unroll
    for (int mf = 0; mf < 2; mf++)
#pragma unroll
        for (int nf = 0; nf < 8; nf++)
#pragma unroll
            for (int i = 0; i < 4; i++) acc[mf][nf][i] = 0.f;

#define ISSUE_STAGE(kt)                                                       \
    {                                                                         \
        const uint32_t sb = s0 + ((kt) % 3) * STAGE_BYTES;                    \
        const int kf = (kt) * 32;                                             \
        _Pragma("unroll")                                                     \
        for (int i = 0; i < 2; i++) cp16(sb + adsto[i], aSrc + kf + asrco[i]);\
        _Pragma("unroll")                                                     \
        for (int i = 0; i < 4; i++) cp16(sb + bdsto[i], bSrc + kf + bsrco[i]);\
    }

    ISSUE_STAGE(0) cp_commit();
    ISSUE_STAGE(1) cp_commit();

    for (int kt = 0; kt < 8; kt++) {
        cp_wait<1>();
        __syncthreads();
        if (kt + 2 < 8) ISSUE_STAGE(kt + 2)
        cp_commit();

        const uint32_t sA  = s0 + (kt % 3) * STAGE_BYTES;
        const uint32_t sBv = sA + 16384;
#pragma unroll
        for (int ks = 0; ks < 4; ks++) {
            const uint32_t kswz = (uint32_t)((((ks * 2 + u2) ^ rp) & 7) << 4);
            uint32_t afr[2][4];
#pragma unroll
            for (int mf = 0; mf < 2; mf++)
                ldsm4(afr[mf][0], afr[mf][1], afr[mf][2], afr[mf][3],
                      sA + (uint32_t)(wm * 4096 + mf * 2048) + uoff + kswz);
            uint32_t b0v[8], b1v[8];
#pragma unroll
            for (int nfp = 0; nfp < 4; nfp++)
                ldsm4(b0v[2 * nfp], b0v[2 * nfp + 1], b1v[2 * nfp], b1v[2 * nfp + 1],
                      sBv + (uint32_t)(wn * 8192 + nfp * 2048) + uoff + kswz);
#pragma unroll
            for (int nf = 0; nf < 8; nf++)
#pragma unroll
                for (int mf = 0; mf < 2; mf++)
                    mma_tf32(acc[mf][nf], afr[mf], b0v[nf], b1v[nf]);
        }
    }

    // Epilogue: bias + feature map + tf32 rounding
    const float* bias = (w == 0) ? bq : ((w == 1) ? bk : bv);
    float* OUT        = (w == 0) ? g_Q : ((w == 1) ? g_K : g_V);
    const bool fmap = (w < 2);
#pragma unroll
    for (int mf = 0; mf < 2; mf++) {
        const int mrow = bm * 128 + wm * 32 + mf * 16 + gr;
#pragma unroll
        for (int nf = 0; nf < 8; nf++) {
            const int col = colbase + wn * 64 + nf * 8 + 2 * gc;
            const float b0v = bias[col];
            const float b1v = bias[col + 1];
            float v0 = acc[mf][nf][0] + b0v;
            float v1 = acc[mf][nf][1] + b1v;
            float v2 = acc[mf][nf][2] + b0v;
            float v3 = acc[mf][nf][3] + b1v;
            if (fmap) {
                v0 = (v0 > 0.f) ? (v0 + 1.f) : __expf(v0);
                v1 = (v1 > 0.f) ? (v1 + 1.f) : __expf(v1);
                v2 = (v2 > 0.f) ? (v2 + 1.f) : __expf(v2);
                v3 = (v3 > 0.f) ? (v3 + 1.f) : __expf(v3);
            }
            v0 = ftf32(v0); v1 = ftf32(v1); v2 = ftf32(v2); v3 = ftf32(v3);
            *(float2*)&OUT[(size_t)mrow * HID + col]       = make_float2(v0, v1);
            *(float2*)&OUT[(size_t)(mrow + 8) * HID + col] = make_float2(v2, v3);
        }
    }
}

// ===================== kv kernel: cp.async double-buffered ===================
// Chunk math: each tile per matrix = 32 rows x 128 fl = 16KB = 1024 chunks
//             = 4/thread x 256 thr.  (R11 bug: was 1/thread = 4x under-copy.)
#define MMA_TILE_BODY(As, Bs, acc)                                            \
    _Pragma("unroll")                                                         \
    for (int ks = 0; ks < 4; ks++) {                                          \
        const int kk = ks * 8;                                                \
        uint32_t afr[2][4];                                                   \
        _Pragma("unroll")                                                     \
        for (int mf = 0; mf < 2; mf++) {                                      \
            const int m0 = wm2 * 32 + mf * 16;                                \
            afr[mf][0] = __float_as_uint(As[kk + gc][m0 + gr]);               \
            afr[mf][1] = __float_as_uint(As[kk + gc][m0 + gr + 8]);           \
            afr[mf][2] = __float_as_uint(As[kk + gc + 4][m0 + gr]);           \
            afr[mf][3] = __float_as_uint(As[kk + gc + 4][m0 + gr + 8]);       \
        }                                                                     \
        _Pragma("unroll")                                                     \
        for (int nf = 0; nf < 8; nf++) {                                      \
            const int n0 = wn2 * 64 + nf * 8;                                 \
            const uint32_t b0 = __float_as_uint(Bs[kk + gc][n0 + gr]);        \
            const uint32_t b1 = __float_as_uint(Bs[kk + gc + 4][n0 + gr]);    \
            mma_tf32(acc[0][nf], afr[0], b0, b1);                             \
            mma_tf32(acc[1][nf], afr[1], b0, b1);                             \
        }                                                                     \
    }

__global__ __launch_bounds__(256) void kv_mma_kernel()
{
    __shared__ float As2[2][32][136];   // V tiles [s][m]
    __shared__ float Bs2[2][32][136];   // K tiles [s][d]
    __shared__ float sKsum[128];

    const int tid  = threadIdx.x;
    const int lane = tid & 31;
    const int warp = tid >> 5;
    const int wm2  = warp & 3;
    const int wn2  = warp >> 2;
    const int gr   = lane >> 2;
    const int gc   = lane & 3;

    const int n = blockIdx.x, h = blockIdx.y;
    const size_t base = (size_t)n * F * HID + (size_t)h * D;

    // 4 chunks/thread: c = i*256+tid -> row = c>>5 (0..31), g = c&31 (16B granule)
    int crow[4], cg4[4];
    uint32_t adst[2][4], bdst[2][4];
#pragma unroll
    for (int i = 0; i < 4; i++) {
        const int c = i * 256 + tid;
        crow[i] = c >> 5;
        cg4[i]  = (c & 31) * 4;
#pragma unroll
        for (int st = 0; st < 2; st++) {
            adst[st][i] = smem_u32(&As2[st][crow[i]][cg4[i]]);
            bdst[st][i] = smem_u32(&Bs2[st][crow[i]][cg4[i]]);
        }
    }

    if (tid < 128) sKsum[tid] = 0.f;
    float4 kacc[4];
#pragma unroll
    for (int i = 0; i < 4; i++) kacc[i] = make_float4(0.f, 0.f, 0.f, 0.f);

    float acc[2][8][4];
#pragma unroll
    for (int mf = 0; mf < 2; mf++)
#pragma unroll
        for (int nf = 0; nf < 8; nf++)
#pragma unroll
            for (int i = 0; i < 4; i++) acc[mf][nf][i] = 0.f;

#define KV_ISSUE(t)                                                           \
    {                                                                         \
        const int _b = (t) & 1;                                               \
        _Pragma("unroll")                                                     \
        for (int i = 0; i < 4; i++) {                                         \
            const size_t so = base + (size_t)((t) * 32 + crow[i]) * HID + cg4[i]; \
            cp16(adst[_b][i], g_V + so);                                      \
            cp16(bdst[_b][i], g_K + so);                                      \
        }                                                                     \
    }

    KV_ISSUE(0) cp_commit();

    for (int t = 0; t < 32; t++) {
        __syncthreads();               // compute(t-1) done; buf (t+1)&1 free
        if (t < 31) { KV_ISSUE(t + 1) cp_commit(); cp_wait<1>(); }
        else cp_wait<0>();
        __syncthreads();               // publish stage t

        const int b = t & 1;
        // Ksum partials: each thread owns 4 distinct (row,granule) K chunks
#pragma unroll
        for (int i = 0; i < 4; i++) {
            float4 kb = *(const float4*)&Bs2[b][crow[i]][cg4[i]];
            kacc[i].x += kb.x; kacc[i].y += kb.y; kacc[i].z += kb.z; kacc[i].w += kb.w;
        }

        MMA_TILE_BODY(As2[b], Bs2[b], acc)
    }

#pragma unroll
    for (int i = 0; i < 4; i++) {
        atomicAdd(&sKsum[cg4[i] + 0], kacc[i].x);
        atomicAdd(&sKsum[cg4[i] + 1], kacc[i].y);
        atomicAdd(&sKsum[cg4[i] + 2], kacc[i].z);
        atomicAdd(&sKsum[cg4[i] + 3], kacc[i].w);
    }
    __syncthreads();

    const size_t nh = (size_t)n * H + h;
    if (tid < 128) g_Ksum[nh * D + tid] = sKsum[tid];

    const size_t kvbase = nh * D * D;
#pragma unroll
    for (int mf = 0; mf < 2; mf++) {
        const int mrow = wm2 * 32 + mf * 16 + gr;
#pragma unroll
        for (int nf = 0; nf < 8; nf++) {
            const int ncol = wn2 * 64 + nf * 8 + 2 * gc;
            *(float2*)&g_KV[kvbase + (size_t)mrow * D + ncol] =
                make_float2(ftf32(acc[mf][nf][0]), ftf32(acc[mf][nf][1]));
            *(float2*)&g_KV[kvbase + (size_t)(mrow + 8) * D + ncol] =
                make_float2(ftf32(acc[mf][nf][2]), ftf32(acc[mf][nf][3]));
        }
    }
}

// ---------------------------------------------------------------------------
// Kernel 3: out = Z * (Q @ KV^T). cp.async 3-stage + ldmatrix (R10, proven).
// Chunk math: A,B tiles each 128x32 fl = 16KB = 1024 chunks = 4/thread x 256.
// ---------------------------------------------------------------------------
#define OSTAGE 32768
__global__ __launch_bounds__(256) void out_mma_kernel(float* __restrict__ out)
{
    extern __shared__ float osm[];
    __shared__ float sZ[128];
    __shared__ float sKs[128];
    const uint32_t s0 = smem_u32(osm);

    const int tid  = threadIdx.x;
    const int lane = tid & 31;
    const int warp = tid >> 5;
    const int wm   = warp & 1;
    const int wn   = warp >> 1;
    const int gr   = lane >> 2;
    const int gc   = lane & 3;

    const int lt = blockIdx.x;
    const int n = blockIdx.y, h = blockIdx.z;
    const int l0 = lt * 128;
    const size_t nh = (size_t)n * H + h;
    const size_t qbase  = ((size_t)n * F + l0) * HID + (size_t)h * D;
    const size_t kvbase = nh * (size_t)D * D;

    const int unit = lane >> 3;
    const int u2   = unit >> 1;
    const int urow = ((unit & 1) << 3) | (lane & 7);
    const uint32_t uoff = (uint32_t)urow * 128;
    const int rp = lane & 7;

    const float* aSrc = g_Q + qbase;
    const float* bSrc = g_KV + kvbase;
    int asrco[4]; int bsrco[4]; uint32_t adsto[4], bdsto[4];
#pragma unroll
    for (int i = 0; i < 4; i++) {
        const int c = i * 256 + tid, row = c >> 3, g = c & 7;
        asrco[i] = row * HID + g * 4;
        bsrco[i] = row * D + g * 4;
        adsto[i] = (uint32_t)(row * 128 + ((g ^ (row & 7)) << 4));
        bdsto[i] = (uint32_t)(16384 + row * 128 + ((g ^ (row & 7)) << 4));
    }

#define O_ISSUE(kt)                                                           \
    {                                                                         \
        const uint32_t sb = s0 + ((kt) % 3) * OSTAGE;                         \
        const int kf = (kt) * 32;                                             \
        _Pragma("unroll")                                                     \
        for (int i = 0; i < 4; i++) {                                         \
            cp16(sb + adsto[i], aSrc + kf + asrco[i]);                        \
            cp16(sb + bdsto[i], bSrc + kf + bsrco[i]);                        \
        }                                                                     \
    }

    O_ISSUE(0) cp_commit();
    O_ISSUE(1) cp_commit();

    if (tid < 128) sKs[tid] = g_Ksum[nh * D + tid];
    __syncwarp();
    {
        float4 kv4;
        {
            const float* ks = g_Ksum + nh * D;
            kv4 = *(const float4*)(ks + lane * 4);
        }
#pragma unroll
        for (int r8 = 0; r8 < 16; r8++) {
            const int row = warp * 16 + r8;
            const float* q = g_Q + qbase + (size_t)row * HID;
            float4 qv = *(const float4*)(q + lane * 4);
            float dd = qv.x * kv4.x + qv.y * kv4.y + qv.z * kv4.z + qv.w * kv4.w;
#pragma unroll
            for (int off = 16; off; off >>= 1) dd += __shfl_xor_sync(0xffffffffu, dd, off);
            if (lane == 0) sZ[row] = 1.f / (dd + EPSV);
        }
    }

    float acc[4][4][4];
#pragma unroll
    for (int mf = 0; mf < 4; mf++)
#pragma unroll
        for (int nf = 0; nf < 4; nf++)
#pragma unroll
            for (int i = 0; i < 4; i++) acc[mf][nf][i] = 0.f;

    for (int kt = 0; kt < 4; kt++) {
        cp_wait<1>();
        __syncthreads();
        if (kt + 2 < 4) O_ISSUE(kt + 2)
        cp_commit();

        const uint32_t sA  = s0 + (kt % 3) * OSTAGE;
        const uint32_t sBv = sA + 16384;
#pragma unroll
        for (int ks = 0; ks < 4; ks++) {
            const uint32_t kswz = (uint32_t)((((ks * 2 + u2) ^ rp) & 7) << 4);
            uint32_t afr[4][4];
#pragma unroll
            for (int mf = 0; mf < 4; mf++)
                ldsm4(afr[mf][0], afr[mf][1], afr[mf][2], afr[mf][3],
                      sA + (uint32_t)(wm * 8192 + mf * 2048) + uoff + kswz);
            uint32_t b0v[4], b1v[4];
#pragma unroll
            for (int nfp = 0; nfp < 2; nfp++)
                ldsm4(b0v[2 * nfp], b0v[2 * nfp + 1], b1v[2 * nfp], b1v[2 * nfp + 1],
                      sBv + (uint32_t)(wn * 4096 + nfp * 2048) + uoff + kswz);
#pragma unroll
            for (int nf = 0; nf < 4; nf++)
#pragma unroll
                for (int mf = 0; mf < 4; mf++)
                    mma_tf32(acc[mf][nf], afr[mf], b0v[nf], b1v[nf]);
        }
    }

#pragma unroll
    for (int mf = 0; mf < 4; mf++) {
        const int row = wm * 64 + mf * 16 + gr;
        const float z0 = sZ[row];
        const float z1 = sZ[row + 8];
        const size_t ob0 = (size_t)(l0 + row) * (NJ * HID) + (size_t)n * HID + (size_t)h * D;
        const size_t ob1 = (size_t)(l0 + row + 8) * (NJ * HID) + (size_t)n * HID + (size_t)h * D;
#pragma unroll
        for (int nf = 0; nf < 4; nf++) {
            const int ncol = wn * 32 + nf * 8 + 2 * gc;
            *(float2*)&out[ob0 + ncol] =
                make_float2(acc[mf][nf][0] * z0, acc[mf][nf][1] * z0);
            *(float2*)&out[ob1 + ncol] =
                make_float2(acc[mf][nf][2] * z1, acc[mf][nf][3] * z1);
        }
    }
}

// ---------------------------------------------------------------------------
extern "C" void kernel_launch(void* const* d_in, const int* in_sizes, int n_in,
                              void* d_out, int out_size)
{
    const float* x  = (const float*)d_in[0];
    const float* Wq = (const float*)d_in[1];
    const float* bq = (const float*)d_in[2];
    const float* Wk = (const float*)d_in[3];
    const float* bk = (const float*)d_in[4];
    const float* Wv = (const float*)d_in[5];
    const float* bv = (const float*)d_in[6];
    float* out = (float*)d_out;

    xr_kernel<<<M_TOT / 8, 256>>>(x);
    dim3 gw(C / 32, HID / 32, 3);
    wt_kernel<<<gw, 256>>>(Wq, Wk, Wv);

    const int smem1 = 3 * STAGE_BYTES;   // 147456 B
    cudaFuncSetAttribute(qkv_mma_kernel,
                         cudaFuncAttributeMaxDynamicSharedMemorySize, smem1);
    dim3 g1(12, M_TOT / 128);
    qkv_mma_kernel<<<g1, 512, smem1>>>(bq, bk, bv);

    dim3 g2(NJ, H);
    kv_mma_kernel<<<g2, 256>>>();

    const int smem3 = 3 * OSTAGE;        // 98304 B
    cudaFuncSetAttribute(out_mma_kernel,
                         cudaFuncAttributeMaxDynamicSharedMemorySize, smem3);
    dim3 g3(F / 128, NJ, H);
    out_mma_kernel<<<g3, 256, smem3>>>(out);
}